// round 9
// baseline (speedup 1.0000x reference)
#include <cuda_runtime.h>
#include <cstdint>

// ---------------------------------------------------------------------------
// DynamicConvBlock: fused 65-tap combined depthwise conv + ReLU + 1x1 conv.
//   x:(8,192,96,96) f32 -> out:(8,64,96,96) f32
// Stage 0: prep_w transposes + duplicates wp into g_wdup[(c,oc)] = (w,w).
// Stage 1: conv kernel (frozen: ~31us, near FFMA2 floor) -> g_mid.
// Stage 2: pointwise v5: 5-stage cp.async pipeline for mid (40 KB smem),
//          ONE sync per chunk, prefetch distance 4; weights read directly
//          from L1-resident g_wdup via broadcast LDG.128 (no smem).
// ---------------------------------------------------------------------------

#define NB   8
#define NC   192
#define NCP  96
#define NH   96
#define NW   96
#define HW   (NH*NW)     // 9216
#define NOC  64
#define TAPS 65
#define PROW 16

// scratch
__device__ float  g_mid[(size_t)NB * NC * HW];     // 56.6 MB
__device__ float2 g_wdup[NC * NOC];                // 96 KB, (w,w) dup'd, [c][oc]

// ---- tap tables ------------------------------------------------------------
__device__ constexpr int SEC_DX[11]   = {-7,-5,-3,-2,-1, 0, 1, 2, 3, 5, 7};
__device__ constexpr int SEC_BASE[11] = {-7,-5,-3,-3,-3,-7,-3,-3,-3,-5,-7};
__device__ constexpr int SEC_W[11]    = {30,26,22,22,22,30,22,22,22,26,30};
__device__ constexpr int SEC_N[11]    = { 3, 3, 7, 7, 7,11, 7, 7, 7, 3, 3};
__device__ constexpr int SEC_OFF[11]  = { 0, 3, 6,13,20,27,38,45,52,59,62};

__device__ constexpr int DY_FLAT[TAPS] = {
    -7,0,7,
    -5,0,5,
    -3,-2,-1,0,1,2,3,
    -3,-2,-1,0,1,2,3,
    -3,-2,-1,0,1,2,3,
    -7,-5,-3,-2,-1,0,1,2,3,5,7,
    -3,-2,-1,0,1,2,3,
    -3,-2,-1,0,1,2,3,
    -3,-2,-1,0,1,2,3,
    -5,0,5,
    -7,0,7
};
__device__ constexpr int DX_FLAT[TAPS] = {
    -7,-7,-7,
    -5,-5,-5,
    -3,-3,-3,-3,-3,-3,-3,
    -2,-2,-2,-2,-2,-2,-2,
    -1,-1,-1,-1,-1,-1,-1,
     0, 0, 0, 0, 0, 0, 0, 0, 0, 0, 0,
     1, 1, 1, 1, 1, 1, 1,
     2, 2, 2, 2, 2, 2, 2,
     3, 3, 3, 3, 3, 3, 3,
     5, 5, 5,
     7, 7, 7
};

// ---- packed f32x2 helpers --------------------------------------------------
__device__ __forceinline__ unsigned long long fma2_(unsigned long long a,
                                                    unsigned long long b,
                                                    unsigned long long c) {
    unsigned long long d;
    asm("fma.rn.f32x2 %0, %1, %2, %3;" : "=l"(d) : "l"(a), "l"(b), "l"(c));
    return d;
}
__device__ __forceinline__ float2 unpk2_(unsigned long long v) {
    float2 f;
    asm("mov.b64 {%0, %1}, %2;" : "=f"(f.x), "=f"(f.y) : "l"(v));
    return f;
}
__device__ __forceinline__ void cpasync16(uint32_t dst, const void* src) {
    asm volatile("cp.async.cg.shared.global [%0], [%1], 16;"
                 :: "r"(dst), "l"(src) : "memory");
}
__device__ __forceinline__ void cpcommit() {
    asm volatile("cp.async.commit_group;" ::: "memory");
}

// ---- fold the 7 weight tensors + a[] into one 65-tap weight ----------------
__device__ __forceinline__ float fold_weight(int c, int t,
                                             const float* __restrict__ a,
                                             const float* __restrict__ k1,
                                             const float* __restrict__ k3,
                                             const float* __restrict__ k5,
                                             const float* __restrict__ k7,
                                             const float* __restrict__ k3d5,
                                             const float* __restrict__ k3d7) {
    int dy = DY_FLAT[t], dx = DX_FLAT[t];
    float w = 0.0f;
    if (abs(dy) <= 3 && abs(dx) <= 3) w += a[4] * k7[c * 49 + (dy + 3) * 7 + (dx + 3)];
    if (abs(dy) <= 2 && abs(dx) <= 2) w += a[3] * k5[c * 25 + (dy + 2) * 5 + (dx + 2)];
    if (abs(dy) <= 1 && abs(dx) <= 1) w += (a[2] + a[5]) * k3[c * 9 + (dy + 1) * 3 + (dx + 1)];
    if (dy == 0 && dx == 0)           w += a[0] + a[1] * k1[c];
    if ((dy == -5 || dy == 0 || dy == 5) && (dx == -5 || dx == 0 || dx == 5))
        w += a[6] * k3d5[c * 9 + (dy / 5 + 1) * 3 + (dx / 5 + 1)];
    if ((dy == -7 || dy == 0 || dy == 7) && (dx == -7 || dx == 0 || dx == 7))
        w += a[7] * k3d7[c * 9 + (dy / 7 + 1) * 3 + (dx / 7 + 1)];
    return w;
}

// ---------------------------------------------------------------------------
// Stage 0: transpose + duplicate wp -> g_wdup[c*64+oc] = (w,w)
// ---------------------------------------------------------------------------
__global__ void prep_w(const float* __restrict__ wp) {
    int i = blockIdx.x * 256 + threadIdx.x;
    if (i < NC * NOC) {
        int c = i >> 6, oc = i & 63;
        float w = wp[oc * NC + c];
        g_wdup[i] = make_float2(w, w);
    }
}

// ---------------------------------------------------------------------------
// Stage 1: depthwise conv + ReLU (frozen).
// ---------------------------------------------------------------------------
#define SM_ROWS 30
#define SM_PITCH 112

__global__ void __launch_bounds__(96)
conv_kernel(const float* __restrict__ x,
            const float* __restrict__ a,
            const float* __restrict__ k1,
            const float* __restrict__ k3,
            const float* __restrict__ k5,
            const float* __restrict__ k7,
            const float* __restrict__ k3d5,
            const float* __restrict__ k3d7) {
    __shared__ float2 sm[SM_ROWS][SM_PITCH];
    __shared__ float2 sw[TAPS];

    const int tid = threadIdx.x;
    const int bc  = blockIdx.y;
    const int b   = bc / NCP;
    const int cp  = bc - b * NCP;
    const int c0  = cp * 2;
    const int h0  = blockIdx.x * PROW;

    {
        float4* smf = reinterpret_cast<float4*>(&sm[0][0]);
        for (int i = tid; i < SM_ROWS * SM_PITCH / 2; i += 96)
            smf[i] = make_float4(0.f, 0.f, 0.f, 0.f);
    }

    for (int i = tid; i < 2 * TAPS; i += 96) {
        int t = i >> 1, half = i & 1;
        float w = fold_weight(c0 + half, t, a, k1, k3, k5, k7, k3d5, k3d7);
        reinterpret_cast<float*>(&sw[t])[half] = w;
    }
    __syncthreads();

    const size_t xbase = ((size_t)b * NC + c0) * HW;
    {
        const int r0 = (h0 >= 7)       ? 0  : 7 - h0;
        const int r1 = (h0 <= NH - 23) ? 30 : (NH + 7 - h0);
        const float* px0 = x + xbase + (size_t)(h0 - 7) * NW + tid;
        for (int r = r0; r < r1; r++) {
            float2 v;
            v.x = px0[(size_t)r * NW];
            v.y = px0[(size_t)r * NW + HW];
            sm[r][tid + 7] = v;
        }
    }
    __syncthreads();

    const int col = tid + 7;
    const unsigned long long* swq = reinterpret_cast<const unsigned long long*>(sw);

    unsigned long long acc[PROW];
#pragma unroll
    for (int p = 0; p < PROW; p++) acc[p] = 0ull;

#pragma unroll
    for (int s = 0; s < 11; s++) {
        const int bse = SEC_BASE[s];
        const int wl  = SEC_W[s];
        const int nd  = SEC_N[s];
        const int off = SEC_OFF[s];
        const int cx  = col + SEC_DX[s];

        unsigned long long wv[11];
#pragma unroll
        for (int j = 0; j < nd; j++) wv[j] = swq[off + j];

#pragma unroll
        for (int i = 0; i < wl; i++) {
            unsigned long long v =
                *reinterpret_cast<const unsigned long long*>(&sm[bse + 7 + i][cx]);
#pragma unroll
            for (int j = 0; j < nd; j++) {
                const int p = i - (DY_FLAT[off + j] - bse);
                if (p >= 0 && p < PROW)
                    acc[p] = fma2_(v, wv[j], acc[p]);
            }
        }
    }

    float* m0 = g_mid + xbase + (size_t)h0 * NW + tid;
#pragma unroll
    for (int p = 0; p < PROW; p++) {
        float2 v = unpk2_(acc[p]);
        v.x = fmaxf(v.x, 0.0f);
        v.y = fmaxf(v.y, 0.0f);
        m0[(size_t)p * NW]      = v.x;
        m0[(size_t)p * NW + HW] = v.y;
    }
}

// ---------------------------------------------------------------------------
// Stage 2: pointwise v5. Block = 256 px x 64 oc, 256 threads.
// K in 24 chunks of 8 channels. 5-stage cp.async pipeline for mid (40 KB),
// prefetch distance 4 chunks, ONE __syncthreads per chunk. Weights read
// per-chunk via broadcast LDG.128 from L1-resident g_wdup (dup'd pairs).
// Thread = 8 px (4 f32x2) x 8 oc; acc = 32 f32x2.
// Hot loop per c: 2 LDS.128 (px) + 4 LDG.128 (w) + 32 FFMA2.
// ---------------------------------------------------------------------------
#define CHUNK    8
#define NCHUNK   (NC / CHUNK)          // 24
#define NSTAGE   5
#define MIDWORDS (CHUNK * 256)         // 2048 (8 KB per stage)

__global__ void __launch_bounds__(256, 2)
pointwise_kernel(float* __restrict__ out) {
    __shared__ float midbuf[NSTAGE][MIDWORDS];          // 40 KB

    const int tid = threadIdx.x;
    const int pixglob = blockIdx.x * 256;               // 256 | 9216
    const int b   = pixglob / HW;
    const int pix = pixglob - b * HW;

    const float* midb = g_mid + (size_t)b * NC * HW + pix;

    const int ocg = tid & 7;                            // 8 oc per group
    const int pxg = tid >> 3;                           // 32 groups x 8 px

    // mid staging: 2 x 16B per thread per chunk
    const int mc0 = tid >> 6, moff = (tid & 63) * 4;    // channels 0..3 of chunk
    const int mc1 = mc0 + 4;                            // channels 4..7

    const uint32_t mid_s   = (uint32_t)__cvta_generic_to_shared(&midbuf[0][0]);
    const uint32_t mid_off = (uint32_t)(mc0 * 256 + moff) * 4;
    const uint32_t mid_off2= (uint32_t)(mc1 * 256 + moff) * 4;

    auto stage = [&](int kc) {
        const int s = kc % NSTAGE;
        const int cbase = kc * CHUNK;
        const uint32_t ms = mid_s + (uint32_t)s * (MIDWORDS * 4);
        cpasync16(ms + mid_off,  midb + (size_t)(cbase + mc0) * HW + moff);
        cpasync16(ms + mid_off2, midb + (size_t)(cbase + mc1) * HW + moff);
        cpcommit();
    };

    // weight base for this thread's 8 oc (4 x ulonglong2 per channel)
    const ulonglong2* wq =
        reinterpret_cast<const ulonglong2*>(g_wdup + ocg * 8);   // + c*32 per ch

    unsigned long long acc[8][4];
#pragma unroll
    for (int j = 0; j < 8; j++)
#pragma unroll
        for (int q = 0; q < 4; q++) acc[j][q] = 0ull;

    stage(0);
    stage(1);
    stage(2);
    stage(3);

#pragma unroll 1
    for (int k = 0; k < NCHUNK; k++) {
        // chunk k resident: pending groups after prior stages = {k..min(k+3,23)}
        if (k <= NCHUNK - 4)
            asm volatile("cp.async.wait_group 3;" ::: "memory");
        else if (k == NCHUNK - 3)
            asm volatile("cp.async.wait_group 2;" ::: "memory");
        else if (k == NCHUNK - 2)
            asm volatile("cp.async.wait_group 1;" ::: "memory");
        else
            asm volatile("cp.async.wait_group 0;" ::: "memory");
        __syncthreads();   // also orders prior iter's consumers before restage

        if (k + 4 < NCHUNK) stage(k + 4);

        const float* mbase = &midbuf[k % NSTAGE][pxg * 8];
        const int cbase = k * CHUNK;

#pragma unroll
        for (int c = 0; c < CHUNK; c++) {
            const float* mrow = mbase + c * 256;
            ulonglong2 a01 = *reinterpret_cast<const ulonglong2*>(mrow);
            ulonglong2 a23 = *reinterpret_cast<const ulonglong2*>(mrow + 4);

            const ulonglong2* wrow = wq + (size_t)(cbase + c) * 32;  // 64 float2 / 2
            ulonglong2 w01 = __ldg(wrow);
            ulonglong2 w23 = __ldg(wrow + 1);
            ulonglong2 w45 = __ldg(wrow + 2);
            ulonglong2 w67 = __ldg(wrow + 3);

            unsigned long long wv[8] = {w01.x, w01.y, w23.x, w23.y,
                                        w45.x, w45.y, w67.x, w67.y};
#pragma unroll
            for (int j = 0; j < 8; j++) {
                acc[j][0] = fma2_(a01.x, wv[j], acc[j][0]);
                acc[j][1] = fma2_(a01.y, wv[j], acc[j][1]);
                acc[j][2] = fma2_(a23.x, wv[j], acc[j][2]);
                acc[j][3] = fma2_(a23.y, wv[j], acc[j][3]);
            }
        }
    }

    // epilogue: out[b][ocg*8+j][pix + pxg*8 + 0..7]
    float* ob = out + ((size_t)b * NOC + ocg * 8) * HW + pix + pxg * 8;
#pragma unroll
    for (int j = 0; j < 8; j++) {
        ulonglong2 lo, hi;
        lo.x = acc[j][0]; lo.y = acc[j][1];
        hi.x = acc[j][2]; hi.y = acc[j][3];
        *reinterpret_cast<ulonglong2*>(ob + (size_t)j * HW)     = lo;
        *reinterpret_cast<ulonglong2*>(ob + (size_t)j * HW + 4) = hi;
    }
}

// ---------------------------------------------------------------------------
extern "C" void kernel_launch(void* const* d_in, const int* in_sizes, int n_in,
                              void* d_out, int out_size) {
    const float* x    = (const float*)d_in[0];
    const float* a    = (const float*)d_in[1];
    const float* k1   = (const float*)d_in[2];
    const float* k3   = (const float*)d_in[3];
    const float* k5   = (const float*)d_in[4];
    const float* k7   = (const float*)d_in[5];
    const float* k3d5 = (const float*)d_in[6];
    const float* k3d7 = (const float*)d_in[7];
    const float* wp   = (const float*)d_in[8];
    float* out = (float*)d_out;

    prep_w<<<(NC * NOC + 255) / 256, 256>>>(wp);
    conv_kernel<<<dim3(NH / PROW, NB * NCP), 96>>>(x, a, k1, k3, k5, k7, k3d5, k3d7);
    pointwise_kernel<<<NB * HW / 256, 256>>>(out);
}

// round 10
// speedup vs baseline: 1.3994x; 1.3994x over previous
#include <cuda_runtime.h>
#include <cstdint>

// ---------------------------------------------------------------------------
// DynamicConvBlock: fused 65-tap combined depthwise conv + ReLU + 1x1 conv.
//   x:(8,192,96,96) f32 -> out:(8,64,96,96) f32
// Stage 1: conv kernel (frozen: ~31us, near FFMA2 floor) -> g_mid.
// Stage 2: pointwise v6 = the measured-78.7us kernel (128 thr, 128px x 64oc,
//          wp transposed oc-pairs in 48KB smem) + ONE change: c-loop batched
//          by 4 with staged LDG.128 mid loads (MLP 2 -> 4).
// ---------------------------------------------------------------------------

#define NB   8
#define NC   192
#define NCP  96
#define NH   96
#define NW   96
#define HW   (NH*NW)     // 9216
#define NOC  64
#define TAPS 65
#define PROW 16

// scratch
__device__ float g_mid[(size_t)NB * NC * HW];      // 56.6 MB

// ---- tap tables ------------------------------------------------------------
__device__ constexpr int SEC_DX[11]   = {-7,-5,-3,-2,-1, 0, 1, 2, 3, 5, 7};
__device__ constexpr int SEC_BASE[11] = {-7,-5,-3,-3,-3,-7,-3,-3,-3,-5,-7};
__device__ constexpr int SEC_W[11]    = {30,26,22,22,22,30,22,22,22,26,30};
__device__ constexpr int SEC_N[11]    = { 3, 3, 7, 7, 7,11, 7, 7, 7, 3, 3};
__device__ constexpr int SEC_OFF[11]  = { 0, 3, 6,13,20,27,38,45,52,59,62};

__device__ constexpr int DY_FLAT[TAPS] = {
    -7,0,7,
    -5,0,5,
    -3,-2,-1,0,1,2,3,
    -3,-2,-1,0,1,2,3,
    -3,-2,-1,0,1,2,3,
    -7,-5,-3,-2,-1,0,1,2,3,5,7,
    -3,-2,-1,0,1,2,3,
    -3,-2,-1,0,1,2,3,
    -3,-2,-1,0,1,2,3,
    -5,0,5,
    -7,0,7
};
__device__ constexpr int DX_FLAT[TAPS] = {
    -7,-7,-7,
    -5,-5,-5,
    -3,-3,-3,-3,-3,-3,-3,
    -2,-2,-2,-2,-2,-2,-2,
    -1,-1,-1,-1,-1,-1,-1,
     0, 0, 0, 0, 0, 0, 0, 0, 0, 0, 0,
     1, 1, 1, 1, 1, 1, 1,
     2, 2, 2, 2, 2, 2, 2,
     3, 3, 3, 3, 3, 3, 3,
     5, 5, 5,
     7, 7, 7
};

// ---- packed f32x2 helpers --------------------------------------------------
__device__ __forceinline__ unsigned long long fma2_(unsigned long long a,
                                                    unsigned long long b,
                                                    unsigned long long c) {
    unsigned long long d;
    asm("fma.rn.f32x2 %0, %1, %2, %3;" : "=l"(d) : "l"(a), "l"(b), "l"(c));
    return d;
}
__device__ __forceinline__ unsigned long long dup2_(float v) {
    unsigned long long d;
    asm("mov.b64 %0, {%1, %1};" : "=l"(d) : "f"(v));
    return d;
}
__device__ __forceinline__ float2 unpk2_(unsigned long long v) {
    float2 f;
    asm("mov.b64 {%0, %1}, %2;" : "=f"(f.x), "=f"(f.y) : "l"(v));
    return f;
}

// ---- fold the 7 weight tensors + a[] into one 65-tap weight ----------------
__device__ __forceinline__ float fold_weight(int c, int t,
                                             const float* __restrict__ a,
                                             const float* __restrict__ k1,
                                             const float* __restrict__ k3,
                                             const float* __restrict__ k5,
                                             const float* __restrict__ k7,
                                             const float* __restrict__ k3d5,
                                             const float* __restrict__ k3d7) {
    int dy = DY_FLAT[t], dx = DX_FLAT[t];
    float w = 0.0f;
    if (abs(dy) <= 3 && abs(dx) <= 3) w += a[4] * k7[c * 49 + (dy + 3) * 7 + (dx + 3)];
    if (abs(dy) <= 2 && abs(dx) <= 2) w += a[3] * k5[c * 25 + (dy + 2) * 5 + (dx + 2)];
    if (abs(dy) <= 1 && abs(dx) <= 1) w += (a[2] + a[5]) * k3[c * 9 + (dy + 1) * 3 + (dx + 1)];
    if (dy == 0 && dx == 0)           w += a[0] + a[1] * k1[c];
    if ((dy == -5 || dy == 0 || dy == 5) && (dx == -5 || dx == 0 || dx == 5))
        w += a[6] * k3d5[c * 9 + (dy / 5 + 1) * 3 + (dx / 5 + 1)];
    if ((dy == -7 || dy == 0 || dy == 7) && (dx == -7 || dx == 0 || dx == 7))
        w += a[7] * k3d7[c * 9 + (dy / 7 + 1) * 3 + (dx / 7 + 1)];
    return w;
}

// ---------------------------------------------------------------------------
// Stage 1: depthwise conv + ReLU (frozen, ~31us).
// ---------------------------------------------------------------------------
#define SM_ROWS 30
#define SM_PITCH 112

__global__ void __launch_bounds__(96)
conv_kernel(const float* __restrict__ x,
            const float* __restrict__ a,
            const float* __restrict__ k1,
            const float* __restrict__ k3,
            const float* __restrict__ k5,
            const float* __restrict__ k7,
            const float* __restrict__ k3d5,
            const float* __restrict__ k3d7) {
    __shared__ float2 sm[SM_ROWS][SM_PITCH];
    __shared__ float2 sw[TAPS];

    const int tid = threadIdx.x;
    const int bc  = blockIdx.y;
    const int b   = bc / NCP;
    const int cp  = bc - b * NCP;
    const int c0  = cp * 2;
    const int h0  = blockIdx.x * PROW;

    {
        float4* smf = reinterpret_cast<float4*>(&sm[0][0]);
        for (int i = tid; i < SM_ROWS * SM_PITCH / 2; i += 96)
            smf[i] = make_float4(0.f, 0.f, 0.f, 0.f);
    }

    for (int i = tid; i < 2 * TAPS; i += 96) {
        int t = i >> 1, half = i & 1;
        float w = fold_weight(c0 + half, t, a, k1, k3, k5, k7, k3d5, k3d7);
        reinterpret_cast<float*>(&sw[t])[half] = w;
    }
    __syncthreads();

    const size_t xbase = ((size_t)b * NC + c0) * HW;
    {
        const int r0 = (h0 >= 7)       ? 0  : 7 - h0;
        const int r1 = (h0 <= NH - 23) ? 30 : (NH + 7 - h0);
        const float* px0 = x + xbase + (size_t)(h0 - 7) * NW + tid;
        for (int r = r0; r < r1; r++) {
            float2 v;
            v.x = px0[(size_t)r * NW];
            v.y = px0[(size_t)r * NW + HW];
            sm[r][tid + 7] = v;
        }
    }
    __syncthreads();

    const int col = tid + 7;
    const unsigned long long* swq = reinterpret_cast<const unsigned long long*>(sw);

    unsigned long long acc[PROW];
#pragma unroll
    for (int p = 0; p < PROW; p++) acc[p] = 0ull;

#pragma unroll
    for (int s = 0; s < 11; s++) {
        const int bse = SEC_BASE[s];
        const int wl  = SEC_W[s];
        const int nd  = SEC_N[s];
        const int off = SEC_OFF[s];
        const int cx  = col + SEC_DX[s];

        unsigned long long wv[11];
#pragma unroll
        for (int j = 0; j < nd; j++) wv[j] = swq[off + j];

#pragma unroll
        for (int i = 0; i < wl; i++) {
            unsigned long long v =
                *reinterpret_cast<const unsigned long long*>(&sm[bse + 7 + i][cx]);
#pragma unroll
            for (int j = 0; j < nd; j++) {
                const int p = i - (DY_FLAT[off + j] - bse);
                if (p >= 0 && p < PROW)
                    acc[p] = fma2_(v, wv[j], acc[p]);
            }
        }
    }

    float* m0 = g_mid + xbase + (size_t)h0 * NW + tid;
#pragma unroll
    for (int p = 0; p < PROW; p++) {
        float2 v = unpk2_(acc[p]);
        v.x = fmaxf(v.x, 0.0f);
        v.y = fmaxf(v.y, 0.0f);
        m0[(size_t)p * NW]      = v.x;
        m0[(size_t)p * NW + HW] = v.y;
    }
}

// ---------------------------------------------------------------------------
// Stage 2: pointwise v6 = measured-78.7us kernel + c-batch-4 staged loads.
// Block = 128 threads = 32 pixel-groups (4 px) x 4 oc-groups (16 oc).
// Block covers 128 px x ALL 64 oc (full mid reuse). wp transposed oc-pairs
// in 48KB smem; broadcast LDS.64 in hot loop. Grid = 576.
// ---------------------------------------------------------------------------
__global__ void __launch_bounds__(128, 4)
pointwise_kernel(const float* __restrict__ wp, float* __restrict__ out) {
    __shared__ float2 ws[NC * 32];                  // ws[c*32+j] = (wp[2j][c], wp[2j+1][c])

    const int tid = threadIdx.x;
    for (int i = tid; i < NC * 32; i += 128) {
        int c = i >> 5, j = i & 31;
        ws[i] = make_float2(__ldg(&wp[(2 * j) * NC + c]),
                            __ldg(&wp[(2 * j + 1) * NC + c]));
    }
    __syncthreads();

    const int pxg = tid & 31;
    const int ocg = tid >> 5;                       // uniform per warp
    const int pixglob = blockIdx.x * 128 + pxg * 4; // 128 | 9216 -> block in one batch
    const int b   = pixglob / HW;
    const int pix = pixglob - b * HW;

    const float* midb = g_mid + (size_t)b * NC * HW + pix;
    const unsigned long long* wbase =
        reinterpret_cast<const unsigned long long*>(ws) + ocg * 8;

    unsigned long long acc[4][8];
#pragma unroll
    for (int p = 0; p < 4; p++)
#pragma unroll
        for (int j = 0; j < 8; j++) acc[p][j] = 0ull;

#pragma unroll 1
    for (int c = 0; c < NC; c += 4) {
        // stage 4 channels of mid up front -> 4 outstanding LDG.128
        float4 m[4];
#pragma unroll
        for (int u = 0; u < 4; u++)
            m[u] = *reinterpret_cast<const float4*>(midb + (size_t)(c + u) * HW);

#pragma unroll
        for (int u = 0; u < 4; u++) {
            unsigned long long m0 = dup2_(m[u].x), m1 = dup2_(m[u].y),
                               m2 = dup2_(m[u].z), m3 = dup2_(m[u].w);
            const unsigned long long* wr = wbase + (c + u) * 32;
#pragma unroll
            for (int j = 0; j < 8; j++) {
                unsigned long long w2 = wr[j];      // broadcast LDS.64
                acc[0][j] = fma2_(m0, w2, acc[0][j]);
                acc[1][j] = fma2_(m1, w2, acc[1][j]);
                acc[2][j] = fma2_(m2, w2, acc[2][j]);
                acc[3][j] = fma2_(m3, w2, acc[3][j]);
            }
        }
    }

    float* ob = out + ((size_t)b * NOC + ocg * 16) * HW + pix;
#pragma unroll
    for (int j = 0; j < 8; j++) {
        float2 a0 = unpk2_(acc[0][j]), a1 = unpk2_(acc[1][j]);
        float2 a2 = unpk2_(acc[2][j]), a3 = unpk2_(acc[3][j]);
        float4 lo = make_float4(a0.x, a1.x, a2.x, a3.x);
        float4 hi = make_float4(a0.y, a1.y, a2.y, a3.y);
        *reinterpret_cast<float4*>(ob + (size_t)(2 * j) * HW)     = lo;
        *reinterpret_cast<float4*>(ob + (size_t)(2 * j + 1) * HW) = hi;
    }
}

// ---------------------------------------------------------------------------
extern "C" void kernel_launch(void* const* d_in, const int* in_sizes, int n_in,
                              void* d_out, int out_size) {
    const float* x    = (const float*)d_in[0];
    const float* a    = (const float*)d_in[1];
    const float* k1   = (const float*)d_in[2];
    const float* k3   = (const float*)d_in[3];
    const float* k5   = (const float*)d_in[4];
    const float* k7   = (const float*)d_in[5];
    const float* k3d5 = (const float*)d_in[6];
    const float* k3d7 = (const float*)d_in[7];
    const float* wp   = (const float*)d_in[8];
    float* out = (float*)d_out;

    conv_kernel<<<dim3(NH / PROW, NB * NCP), 96>>>(x, a, k1, k3, k5, k7, k3d5, k3d7);
    pointwise_kernel<<<NB * HW / 128, 128>>>(wp, out);
}

// round 11
// speedup vs baseline: 1.6489x; 1.1783x over previous
#include <cuda_runtime.h>
#include <cstdint>

// ---------------------------------------------------------------------------
// DynamicConvBlock: fused 65-tap combined depthwise conv + ReLU + 1x1 conv.
//   x:(8,192,96,96) f32 -> out:(8,64,96,96) f32
// Stage 0: prep_w_frag: W -> hi/lo TF32 A-fragments in mma lane order.
// Stage 1: conv kernel (frozen, ~31us) -> g_mid.
// Stage 2: pointwise_tc: mma.sync.m16n8k8 TF32, 3xTF32 split.
//          Block = 64oc x 64px, warp = m16 x n64, K=192 in 24 steps.
// ---------------------------------------------------------------------------

#define NB   8
#define NC   192
#define NCP  96
#define NH   96
#define NW   96
#define HW   (NH*NW)     // 9216
#define NOC  64
#define TAPS 65
#define PROW 16
#define KSTEPS 24        // 192 / 8

// scratch
__device__ float g_mid[(size_t)NB * NC * HW];      // 56.6 MB
__device__ uint4 g_wah[4 * KSTEPS * 32];           // A-fragments hi (48 KB)
__device__ uint4 g_wal[4 * KSTEPS * 32];           // A-fragments lo (48 KB)

// ---- tap tables ------------------------------------------------------------
__device__ constexpr int SEC_DX[11]   = {-7,-5,-3,-2,-1, 0, 1, 2, 3, 5, 7};
__device__ constexpr int SEC_BASE[11] = {-7,-5,-3,-3,-3,-7,-3,-3,-3,-5,-7};
__device__ constexpr int SEC_W[11]    = {30,26,22,22,22,30,22,22,22,26,30};
__device__ constexpr int SEC_N[11]    = { 3, 3, 7, 7, 7,11, 7, 7, 7, 3, 3};
__device__ constexpr int SEC_OFF[11]  = { 0, 3, 6,13,20,27,38,45,52,59,62};

__device__ constexpr int DY_FLAT[TAPS] = {
    -7,0,7,
    -5,0,5,
    -3,-2,-1,0,1,2,3,
    -3,-2,-1,0,1,2,3,
    -3,-2,-1,0,1,2,3,
    -7,-5,-3,-2,-1,0,1,2,3,5,7,
    -3,-2,-1,0,1,2,3,
    -3,-2,-1,0,1,2,3,
    -3,-2,-1,0,1,2,3,
    -5,0,5,
    -7,0,7
};
__device__ constexpr int DX_FLAT[TAPS] = {
    -7,-7,-7,
    -5,-5,-5,
    -3,-3,-3,-3,-3,-3,-3,
    -2,-2,-2,-2,-2,-2,-2,
    -1,-1,-1,-1,-1,-1,-1,
     0, 0, 0, 0, 0, 0, 0, 0, 0, 0, 0,
     1, 1, 1, 1, 1, 1, 1,
     2, 2, 2, 2, 2, 2, 2,
     3, 3, 3, 3, 3, 3, 3,
     5, 5, 5,
     7, 7, 7
};

// ---- helpers ---------------------------------------------------------------
__device__ __forceinline__ unsigned long long fma2_(unsigned long long a,
                                                    unsigned long long b,
                                                    unsigned long long c) {
    unsigned long long d;
    asm("fma.rn.f32x2 %0, %1, %2, %3;" : "=l"(d) : "l"(a), "l"(b), "l"(c));
    return d;
}
__device__ __forceinline__ float2 unpk2_(unsigned long long v) {
    float2 f;
    asm("mov.b64 {%0, %1}, %2;" : "=f"(f.x), "=f"(f.y) : "l"(v));
    return f;
}
__device__ __forceinline__ uint32_t f2tf32(float v) {
    uint32_t r;
    asm("cvt.rna.tf32.f32 %0, %1;" : "=r"(r) : "f"(v));
    return r;
}
__device__ __forceinline__ void mma_tf32(float* d, uint4 a,
                                         uint32_t b0, uint32_t b1) {
    asm("mma.sync.aligned.m16n8k8.row.col.f32.tf32.tf32.f32 "
        "{%0,%1,%2,%3}, {%4,%5,%6,%7}, {%8,%9}, {%0,%1,%2,%3};"
        : "+f"(d[0]), "+f"(d[1]), "+f"(d[2]), "+f"(d[3])
        : "r"(a.x), "r"(a.y), "r"(a.z), "r"(a.w), "r"(b0), "r"(b1));
}

// ---- fold the 7 weight tensors + a[] into one 65-tap weight ----------------
__device__ __forceinline__ float fold_weight(int c, int t,
                                             const float* __restrict__ a,
                                             const float* __restrict__ k1,
                                             const float* __restrict__ k3,
                                             const float* __restrict__ k5,
                                             const float* __restrict__ k7,
                                             const float* __restrict__ k3d5,
                                             const float* __restrict__ k3d7) {
    int dy = DY_FLAT[t], dx = DX_FLAT[t];
    float w = 0.0f;
    if (abs(dy) <= 3 && abs(dx) <= 3) w += a[4] * k7[c * 49 + (dy + 3) * 7 + (dx + 3)];
    if (abs(dy) <= 2 && abs(dx) <= 2) w += a[3] * k5[c * 25 + (dy + 2) * 5 + (dx + 2)];
    if (abs(dy) <= 1 && abs(dx) <= 1) w += (a[2] + a[5]) * k3[c * 9 + (dy + 1) * 3 + (dx + 1)];
    if (dy == 0 && dx == 0)           w += a[0] + a[1] * k1[c];
    if ((dy == -5 || dy == 0 || dy == 5) && (dx == -5 || dx == 0 || dx == 5))
        w += a[6] * k3d5[c * 9 + (dy / 5 + 1) * 3 + (dx / 5 + 1)];
    if ((dy == -7 || dy == 0 || dy == 7) && (dx == -7 || dx == 0 || dx == 7))
        w += a[7] * k3d7[c * 9 + (dy / 7 + 1) * 3 + (dx / 7 + 1)];
    return w;
}

// ---------------------------------------------------------------------------
// Stage 0: build hi/lo TF32 A-fragments for mma.m16n8k8.
// Fragment f = mt*24+ks, lane l:
//   a0 = W[16mt + l/4      ][8ks + l%4    ]
//   a1 = W[16mt + l/4 + 8  ][8ks + l%4    ]
//   a2 = W[16mt + l/4      ][8ks + l%4 + 4]
//   a3 = W[16mt + l/4 + 8  ][8ks + l%4 + 4]
// ---------------------------------------------------------------------------
__global__ void prep_w_frag(const float* __restrict__ wp) {
    int i = blockIdx.x * 256 + threadIdx.x;
    if (i >= 4 * KSTEPS * 32) return;
    int lane = i & 31;
    int f    = i >> 5;
    int mt   = f / KSTEPS;
    int ks   = f - mt * KSTEPS;
    int r = mt * 16 + (lane >> 2);
    int c = ks * 8 + (lane & 3);

    float a0 = wp[r * NC + c];
    float a1 = wp[(r + 8) * NC + c];
    float a2 = wp[r * NC + c + 4];
    float a3 = wp[(r + 8) * NC + c + 4];

    uint32_t h0 = f2tf32(a0), h1 = f2tf32(a1), h2 = f2tf32(a2), h3 = f2tf32(a3);
    g_wah[i] = make_uint4(h0, h1, h2, h3);
    g_wal[i] = make_uint4(f2tf32(a0 - __uint_as_float(h0)),
                          f2tf32(a1 - __uint_as_float(h1)),
                          f2tf32(a2 - __uint_as_float(h2)),
                          f2tf32(a3 - __uint_as_float(h3)));
}

// ---------------------------------------------------------------------------
// Stage 1: depthwise conv + ReLU (frozen, ~31us).
// ---------------------------------------------------------------------------
#define SM_ROWS 30
#define SM_PITCH 112

__global__ void __launch_bounds__(96)
conv_kernel(const float* __restrict__ x,
            const float* __restrict__ a,
            const float* __restrict__ k1,
            const float* __restrict__ k3,
            const float* __restrict__ k5,
            const float* __restrict__ k7,
            const float* __restrict__ k3d5,
            const float* __restrict__ k3d7) {
    __shared__ float2 sm[SM_ROWS][SM_PITCH];
    __shared__ float2 sw[TAPS];

    const int tid = threadIdx.x;
    const int bc  = blockIdx.y;
    const int b   = bc / NCP;
    const int cp  = bc - b * NCP;
    const int c0  = cp * 2;
    const int h0  = blockIdx.x * PROW;

    {
        float4* smf = reinterpret_cast<float4*>(&sm[0][0]);
        for (int i = tid; i < SM_ROWS * SM_PITCH / 2; i += 96)
            smf[i] = make_float4(0.f, 0.f, 0.f, 0.f);
    }

    for (int i = tid; i < 2 * TAPS; i += 96) {
        int t = i >> 1, half = i & 1;
        float w = fold_weight(c0 + half, t, a, k1, k3, k5, k7, k3d5, k3d7);
        reinterpret_cast<float*>(&sw[t])[half] = w;
    }
    __syncthreads();

    const size_t xbase = ((size_t)b * NC + c0) * HW;
    {
        const int r0 = (h0 >= 7)       ? 0  : 7 - h0;
        const int r1 = (h0 <= NH - 23) ? 30 : (NH + 7 - h0);
        const float* px0 = x + xbase + (size_t)(h0 - 7) * NW + tid;
        for (int r = r0; r < r1; r++) {
            float2 v;
            v.x = px0[(size_t)r * NW];
            v.y = px0[(size_t)r * NW + HW];
            sm[r][tid + 7] = v;
        }
    }
    __syncthreads();

    const int col = tid + 7;
    const unsigned long long* swq = reinterpret_cast<const unsigned long long*>(sw);

    unsigned long long acc[PROW];
#pragma unroll
    for (int p = 0; p < PROW; p++) acc[p] = 0ull;

#pragma unroll
    for (int s = 0; s < 11; s++) {
        const int bse = SEC_BASE[s];
        const int wl  = SEC_W[s];
        const int nd  = SEC_N[s];
        const int off = SEC_OFF[s];
        const int cx  = col + SEC_DX[s];

        unsigned long long wv[11];
#pragma unroll
        for (int j = 0; j < nd; j++) wv[j] = swq[off + j];

#pragma unroll
        for (int i = 0; i < wl; i++) {
            unsigned long long v =
                *reinterpret_cast<const unsigned long long*>(&sm[bse + 7 + i][cx]);
#pragma unroll
            for (int j = 0; j < nd; j++) {
                const int p = i - (DY_FLAT[off + j] - bse);
                if (p >= 0 && p < PROW)
                    acc[p] = fma2_(v, wv[j], acc[p]);
            }
        }
    }

    float* m0 = g_mid + xbase + (size_t)h0 * NW + tid;
#pragma unroll
    for (int p = 0; p < PROW; p++) {
        float2 v = unpk2_(acc[p]);
        v.x = fmaxf(v.x, 0.0f);
        v.y = fmaxf(v.y, 0.0f);
        m0[(size_t)p * NW]      = v.x;
        m0[(size_t)p * NW + HW] = v.y;
    }
}

// ---------------------------------------------------------------------------
// Stage 2: pointwise 1x1 conv 192->64 on tensor cores.
// out[64, 9216*8] = W[64,192] @ mid[192, px], 3xTF32 (HiHi + HiLo + LoHi).
// Block = 128 thr (4 warps) = 64 oc x 64 px tile; warp mt = m16 slab x n64.
// Per k8-step: A hi/lo via 2 LDG.128 (fragment tables, L1/L2-hot);
// B loaded per-subtile from g_mid (each element once chip-wide), split
// hi/lo in registers; 24 mma per warp-step. Grid = 1152.
// B-fragment (m16n8k8 row.col): b0 = M[k0 + l%4][n0 + l/4],
//                               b1 = M[k0 + l%4 + 4][n0 + l/4].
// C-fragment: c0,c1 = row l/4,    cols 2*(l%4)+{0,1};
//             c2,c3 = row l/4 +8, same cols.
// ---------------------------------------------------------------------------
__global__ void __launch_bounds__(128)
pointwise_tc(float* __restrict__ out) {
    const int tid  = threadIdx.x;
    const int lane = tid & 31;
    const int mt   = tid >> 5;                      // 0..3 (m16 slab)

    const int pixglob = blockIdx.x * 64;            // 64 | 9216
    const int b   = pixglob / HW;
    const int pix = pixglob - b * HW;

    const float* midb = g_mid + (size_t)b * NC * HW + pix;
    const int kr = lane & 3;                        // k row in group
    const int np = lane >> 2;                       // px in subtile

    const uint4* wah = g_wah + mt * (KSTEPS * 32) + lane;
    const uint4* wal = g_wal + mt * (KSTEPS * 32) + lane;

    float acc[8][4];
#pragma unroll
    for (int s = 0; s < 8; s++)
#pragma unroll
        for (int q = 0; q < 4; q++) acc[s][q] = 0.0f;

#pragma unroll 1
    for (int ks = 0; ks < KSTEPS; ks++) {
        const uint4 Ah = wah[ks * 32];
        const uint4 Al = wal[ks * 32];
        const float* mk = midb + (size_t)(ks * 8 + kr) * HW + np;

        // load raw B values for all 8 subtiles first (MLP=16)
        float v0[8], v1[8];
#pragma unroll
        for (int s = 0; s < 8; s++) {
            v0[s] = mk[s * 8];
            v1[s] = mk[(size_t)4 * HW + s * 8];
        }

#pragma unroll
        for (int s = 0; s < 8; s++) {
            uint32_t bh0 = f2tf32(v0[s]);
            uint32_t bh1 = f2tf32(v1[s]);
            uint32_t bl0 = f2tf32(v0[s] - __uint_as_float(bh0));
            uint32_t bl1 = f2tf32(v1[s] - __uint_as_float(bh1));
            mma_tf32(acc[s], Ah, bh0, bh1);
            mma_tf32(acc[s], Ah, bl0, bl1);
            mma_tf32(acc[s], Al, bh0, bh1);
        }
    }

    // epilogue
    const int g  = lane >> 2;
    const int t4 = lane & 3;
    float* o0 = out + ((size_t)(b * NOC + mt * 16 + g)) * HW + pix + 2 * t4;
    float* o1 = o0 + (size_t)8 * HW;
#pragma unroll
    for (int s = 0; s < 8; s++) {
        *reinterpret_cast<float2*>(o0 + s * 8) = make_float2(acc[s][0], acc[s][1]);
        *reinterpret_cast<float2*>(o1 + s * 8) = make_float2(acc[s][2], acc[s][3]);
    }
}

// ---------------------------------------------------------------------------
extern "C" void kernel_launch(void* const* d_in, const int* in_sizes, int n_in,
                              void* d_out, int out_size) {
    const float* x    = (const float*)d_in[0];
    const float* a    = (const float*)d_in[1];
    const float* k1   = (const float*)d_in[2];
    const float* k3   = (const float*)d_in[3];
    const float* k5   = (const float*)d_in[4];
    const float* k7   = (const float*)d_in[5];
    const float* k3d5 = (const float*)d_in[6];
    const float* k3d7 = (const float*)d_in[7];
    const float* wp   = (const float*)d_in[8];
    float* out = (float*)d_out;

    prep_w_frag<<<(4 * KSTEPS * 32 + 255) / 256, 256>>>(wp);
    conv_kernel<<<dim3(NH / PROW, NB * NCP), 96>>>(x, a, k1, k3, k5, k7, k3d5, k3d7);
    pointwise_tc<<<NB * HW / 64, 128>>>(out);
}

// round 13
// speedup vs baseline: 2.1357x; 1.2952x over previous
#include <cuda_runtime.h>
#include <cstdint>

// ---------------------------------------------------------------------------
// DynamicConvBlock: fused 65-tap combined depthwise conv + ReLU + 1x1 conv.
//   x:(8,192,96,96) f32 -> out:(8,64,96,96) f32
// Stage 0: prep_w_frag: W -> bf16 hi/lo A-fragments (m16n8k16 lane order).
// Stage 1: conv kernel (frozen, ~31us) -> g_mid.
// Stage 2: pointwise_tc2: mma.sync.m16n8k16 bf16, 3-pass bf16 split.
//          Warp = all 64 oc x 32 px (no B replication); block = 128 px.
// ---------------------------------------------------------------------------

#define NB   8
#define NC   192
#define NCP  96
#define NH   96
#define NW   96
#define HW   (NH*NW)     // 9216
#define NOC  64
#define TAPS 65
#define PROW 16
#define KS16 12          // 192 / 16

// scratch
__device__ float g_mid[(size_t)NB * NC * HW];      // 56.6 MB
__device__ uint4 g_wah[4 * KS16 * 32];             // A-fragments hi (24 KB)
__device__ uint4 g_wal[4 * KS16 * 32];             // A-fragments lo (24 KB)

// ---- tap tables ------------------------------------------------------------
__device__ constexpr int SEC_DX[11]   = {-7,-5,-3,-2,-1, 0, 1, 2, 3, 5, 7};
__device__ constexpr int SEC_BASE[11] = {-7,-5,-3,-3,-3,-7,-3,-3,-3,-5,-7};
__device__ constexpr int SEC_W[11]    = {30,26,22,22,22,30,22,22,22,26,30};
__device__ constexpr int SEC_N[11]    = { 3, 3, 7, 7, 7,11, 7, 7, 7, 3, 3};
__device__ constexpr int SEC_OFF[11]  = { 0, 3, 6,13,20,27,38,45,52,59,62};

__device__ constexpr int DY_FLAT[TAPS] = {
    -7,0,7, -5,0,5,
    -3,-2,-1,0,1,2,3, -3,-2,-1,0,1,2,3, -3,-2,-1,0,1,2,3,
    -7,-5,-3,-2,-1,0,1,2,3,5,7,
    -3,-2,-1,0,1,2,3, -3,-2,-1,0,1,2,3, -3,-2,-1,0,1,2,3,
    -5,0,5, -7,0,7
};
__device__ constexpr int DX_FLAT[TAPS] = {
    -7,-7,-7, -5,-5,-5,
    -3,-3,-3,-3,-3,-3,-3, -2,-2,-2,-2,-2,-2,-2, -1,-1,-1,-1,-1,-1,-1,
     0,0,0,0,0,0,0,0,0,0,0,
     1,1,1,1,1,1,1, 2,2,2,2,2,2,2, 3,3,3,3,3,3,3,
     5,5,5, 7,7,7
};

// ---- helpers ---------------------------------------------------------------
__device__ __forceinline__ unsigned long long fma2_(unsigned long long a,
                                                    unsigned long long b,
                                                    unsigned long long c) {
    unsigned long long d;
    asm("fma.rn.f32x2 %0, %1, %2, %3;" : "=l"(d) : "l"(a), "l"(b), "l"(c));
    return d;
}
__device__ __forceinline__ float2 unpk2_(unsigned long long v) {
    float2 f;
    asm("mov.b64 {%0, %1}, %2;" : "=f"(f.x), "=f"(f.y) : "l"(v));
    return f;
}
// pack two f32 -> bf16x2 (first arg -> low half)
__device__ __forceinline__ uint32_t packbf(float lo, float hi) {
    uint32_t r;
    asm("cvt.rn.bf16x2.f32 %0, %1, %2;" : "=r"(r) : "f"(hi), "f"(lo));
    return r;
}
__device__ __forceinline__ float bflo(uint32_t v) {
    return __uint_as_float(v << 16);
}
__device__ __forceinline__ float bfhi(uint32_t v) {
    return __uint_as_float(v & 0xFFFF0000u);
}
__device__ __forceinline__ void mma_bf16(float* d, uint4 a,
                                         uint32_t b0, uint32_t b1) {
    asm("mma.sync.aligned.m16n8k16.row.col.f32.bf16.bf16.f32 "
        "{%0,%1,%2,%3}, {%4,%5,%6,%7}, {%8,%9}, {%0,%1,%2,%3};"
        : "+f"(d[0]), "+f"(d[1]), "+f"(d[2]), "+f"(d[3])
        : "r"(a.x), "r"(a.y), "r"(a.z), "r"(a.w), "r"(b0), "r"(b1));
}

// ---- fold the 7 weight tensors + a[] into one 65-tap weight ----------------
__device__ __forceinline__ float fold_weight(int c, int t,
                                             const float* __restrict__ a,
                                             const float* __restrict__ k1,
                                             const float* __restrict__ k3,
                                             const float* __restrict__ k5,
                                             const float* __restrict__ k7,
                                             const float* __restrict__ k3d5,
                                             const float* __restrict__ k3d7) {
    int dy = DY_FLAT[t], dx = DX_FLAT[t];
    float w = 0.0f;
    if (abs(dy) <= 3 && abs(dx) <= 3) w += a[4] * k7[c * 49 + (dy + 3) * 7 + (dx + 3)];
    if (abs(dy) <= 2 && abs(dx) <= 2) w += a[3] * k5[c * 25 + (dy + 2) * 5 + (dx + 2)];
    if (abs(dy) <= 1 && abs(dx) <= 1) w += (a[2] + a[5]) * k3[c * 9 + (dy + 1) * 3 + (dx + 1)];
    if (dy == 0 && dx == 0)           w += a[0] + a[1] * k1[c];
    if ((dy == -5 || dy == 0 || dy == 5) && (dx == -5 || dx == 0 || dx == 5))
        w += a[6] * k3d5[c * 9 + (dy / 5 + 1) * 3 + (dx / 5 + 1)];
    if ((dy == -7 || dy == 0 || dy == 7) && (dx == -7 || dx == 0 || dx == 7))
        w += a[7] * k3d7[c * 9 + (dy / 7 + 1) * 3 + (dx / 7 + 1)];
    return w;
}

// ---------------------------------------------------------------------------
// Stage 0: bf16 hi/lo A-fragments for mma.m16n8k16.row (A = W[64,192]).
// Fragment f = mt*12+ks, lane l (r = 16mt + l/4, c = 16ks + 2*(l%4)):
//   a0 = {W[r][c],     W[r][c+1]}     a1 = {W[r+8][c],   W[r+8][c+1]}
//   a2 = {W[r][c+8],   W[r][c+9]}     a3 = {W[r+8][c+8], W[r+8][c+9]}
// ---------------------------------------------------------------------------
__global__ void prep_w_frag(const float* __restrict__ wp) {
    int i = blockIdx.x * 256 + threadIdx.x;
    if (i >= 4 * KS16 * 32) return;
    int lane = i & 31;
    int f    = i >> 5;
    int mt   = f / KS16;
    int ks   = f - mt * KS16;
    int r = mt * 16 + (lane >> 2);
    int c = ks * 16 + (lane & 3) * 2;

    float e[8] = { wp[r * NC + c],           wp[r * NC + c + 1],
                   wp[(r + 8) * NC + c],     wp[(r + 8) * NC + c + 1],
                   wp[r * NC + c + 8],       wp[r * NC + c + 9],
                   wp[(r + 8) * NC + c + 8], wp[(r + 8) * NC + c + 9] };

    uint32_t hi[4], lo[4];
#pragma unroll
    for (int q = 0; q < 4; q++) {
        float x0 = e[2 * q], x1 = e[2 * q + 1];
        uint32_t h = packbf(x0, x1);
        hi[q] = h;
        lo[q] = packbf(x0 - bflo(h), x1 - bfhi(h));
    }
    g_wah[i] = make_uint4(hi[0], hi[1], hi[2], hi[3]);
    g_wal[i] = make_uint4(lo[0], lo[1], lo[2], lo[3]);
}

// ---------------------------------------------------------------------------
// Stage 1: depthwise conv + ReLU (frozen, ~31us).
// ---------------------------------------------------------------------------
#define SM_ROWS 30
#define SM_PITCH 112

__global__ void __launch_bounds__(96)
conv_kernel(const float* __restrict__ x,
            const float* __restrict__ a,
            const float* __restrict__ k1,
            const float* __restrict__ k3,
            const float* __restrict__ k5,
            const float* __restrict__ k7,
            const float* __restrict__ k3d5,
            const float* __restrict__ k3d7) {
    __shared__ float2 sm[SM_ROWS][SM_PITCH];
    __shared__ float2 sw[TAPS];

    const int tid = threadIdx.x;
    const int bc  = blockIdx.y;
    const int b   = bc / NCP;
    const int cp  = bc - b * NCP;
    const int c0  = cp * 2;
    const int h0  = blockIdx.x * PROW;

    {
        float4* smf = reinterpret_cast<float4*>(&sm[0][0]);
        for (int i = tid; i < SM_ROWS * SM_PITCH / 2; i += 96)
            smf[i] = make_float4(0.f, 0.f, 0.f, 0.f);
    }

    for (int i = tid; i < 2 * TAPS; i += 96) {
        int t = i >> 1, half = i & 1;
        float w = fold_weight(c0 + half, t, a, k1, k3, k5, k7, k3d5, k3d7);
        reinterpret_cast<float*>(&sw[t])[half] = w;
    }
    __syncthreads();

    const size_t xbase = ((size_t)b * NC + c0) * HW;
    {
        const int r0 = (h0 >= 7)       ? 0  : 7 - h0;
        const int r1 = (h0 <= NH - 23) ? 30 : (NH + 7 - h0);
        const float* px0 = x + xbase + (size_t)(h0 - 7) * NW + tid;
        for (int r = r0; r < r1; r++) {
            float2 v;
            v.x = px0[(size_t)r * NW];
            v.y = px0[(size_t)r * NW + HW];
            sm[r][tid + 7] = v;
        }
    }
    __syncthreads();

    const int col = tid + 7;
    const unsigned long long* swq = reinterpret_cast<const unsigned long long*>(sw);

    unsigned long long acc[PROW];
#pragma unroll
    for (int p = 0; p < PROW; p++) acc[p] = 0ull;

#pragma unroll
    for (int s = 0; s < 11; s++) {
        const int bse = SEC_BASE[s];
        const int wl  = SEC_W[s];
        const int nd  = SEC_N[s];
        const int off = SEC_OFF[s];
        const int cx  = col + SEC_DX[s];

        unsigned long long wv[11];
#pragma unroll
        for (int j = 0; j < nd; j++) wv[j] = swq[off + j];

#pragma unroll
        for (int i = 0; i < wl; i++) {
            unsigned long long v =
                *reinterpret_cast<const unsigned long long*>(&sm[bse + 7 + i][cx]);
#pragma unroll
            for (int j = 0; j < nd; j++) {
                const int p = i - (DY_FLAT[off + j] - bse);
                if (p >= 0 && p < PROW)
                    acc[p] = fma2_(v, wv[j], acc[p]);
            }
        }
    }

    float* m0 = g_mid + xbase + (size_t)h0 * NW + tid;
#pragma unroll
    for (int p = 0; p < PROW; p++) {
        float2 v = unpk2_(acc[p]);
        v.x = fmaxf(v.x, 0.0f);
        v.y = fmaxf(v.y, 0.0f);
        m0[(size_t)p * NW]      = v.x;
        m0[(size_t)p * NW + HW] = v.y;
    }
}

// ---------------------------------------------------------------------------
// Stage 2: pointwise 1x1 conv 192->64, mma.sync.m16n8k16 bf16, 3-pass split.
// Block = 128 thr (4 warps), block tile = 64 oc x 128 px.
// Warp = ALL 4 m-slabs x 4 n8-subtiles (32 px) -> no B replication: every
// mid element loaded exactly once chip-wide.
// B-fragment (row.col): n = n0 + l/4; b0 = {M[k0][n],M[k0+1][n]},
//   b1 = {M[k0+8][n],M[k0+9][n]}, k0 = 16ks + 2*(l%4).
// C-fragment: c0,c1 = row l/4, cols 2*(l%4)+{0,1}; c2,c3 = row+8.
// ---------------------------------------------------------------------------
__global__ void __launch_bounds__(128)
pointwise_tc2(float* __restrict__ out) {
    const int tid  = threadIdx.x;
    const int lane = tid & 31;
    const int wt   = tid >> 5;                      // warp's px quarter

    const int pixglob = blockIdx.x * 128 + wt * 32; // 128 | 9216
    const int b   = pixglob / HW;
    const int pix = pixglob - b * HW;

    const int kr2 = (lane & 3) * 2;                 // k pair base
    const int np  = lane >> 2;                      // px within subtile

    const float* midb = g_mid + (size_t)b * NC * HW + pix + np;
    const uint4* wah = g_wah + lane;
    const uint4* wal = g_wal + lane;

    float acc[4][4][4];                             // [mt][subtile][4]
#pragma unroll
    for (int m = 0; m < 4; m++)
#pragma unroll
        for (int s = 0; s < 4; s++)
#pragma unroll
            for (int q = 0; q < 4; q++) acc[m][s][q] = 0.0f;

#pragma unroll 1
    for (int ks = 0; ks < KS16; ks++) {
        // A fragments: 4 m-slabs, hi+lo (L1-hot tables)
        uint4 Ah[4], Al[4];
#pragma unroll
        for (int m = 0; m < 4; m++) {
            Ah[m] = wah[(m * KS16 + ks) * 32];
            Al[m] = wal[(m * KS16 + ks) * 32];
        }

        // B values: 4 subtiles x 4 k-rows, all loads issued first (MLP=16)
        const float* mk = midb + (size_t)(ks * 16 + kr2) * HW;
        float v[4][4];
#pragma unroll
        for (int s = 0; s < 4; s++) {
            v[s][0] = mk[s * 8];
            v[s][1] = mk[(size_t)1 * HW + s * 8];
            v[s][2] = mk[(size_t)8 * HW + s * 8];
            v[s][3] = mk[(size_t)9 * HW + s * 8];
        }

#pragma unroll
        for (int s = 0; s < 4; s++) {
            uint32_t bh0 = packbf(v[s][0], v[s][1]);
            uint32_t bh1 = packbf(v[s][2], v[s][3]);
            uint32_t bl0 = packbf(v[s][0] - bflo(bh0), v[s][1] - bfhi(bh0));
            uint32_t bl1 = packbf(v[s][2] - bflo(bh1), v[s][3] - bfhi(bh1));
#pragma unroll
            for (int m = 0; m < 4; m++) {
                mma_bf16(acc[m][s], Ah[m], bh0, bh1);
                mma_bf16(acc[m][s], Ah[m], bl0, bl1);
                mma_bf16(acc[m][s], Al[m], bh0, bh1);
            }
        }
    }

    // epilogue
    const int g  = lane >> 2;
    const int t4 = lane & 3;
#pragma unroll
    for (int m = 0; m < 4; m++) {
        float* o0 = out + ((size_t)(b * NOC + m * 16 + g)) * HW + pix + 2 * t4;
        float* o1 = o0 + (size_t)8 * HW;
#pragma unroll
        for (int s = 0; s < 4; s++) {
            *reinterpret_cast<float2*>(o0 + s * 8) =
                make_float2(acc[m][s][0], acc[m][s][1]);
            *reinterpret_cast<float2*>(o1 + s * 8) =
                make_float2(acc[m][s][2], acc[m][s][3]);
        }
    }
}

// ---------------------------------------------------------------------------
extern "C" void kernel_launch(void* const* d_in, const int* in_sizes, int n_in,
                              void* d_out, int out_size) {
    const float* x    = (const float*)d_in[0];
    const float* a    = (const float*)d_in[1];
    const float* k1   = (const float*)d_in[2];
    const float* k3   = (const float*)d_in[3];
    const float* k5   = (const float*)d_in[4];
    const float* k7   = (const float*)d_in[5];
    const float* k3d5 = (const float*)d_in[6];
    const float* k3d7 = (const float*)d_in[7];
    const float* wp   = (const float*)d_in[8];
    float* out = (float*)d_out;

    prep_w_frag<<<(4 * KS16 * 32 + 255) / 256, 256>>>(wp);
    conv_kernel<<<dim3(NH / PROW, NB * NCP), 96>>>(x, a, k1, k3, k5, k7, k3d5, k3d7);
    pointwise_tc2<<<NB * HW / 128, 128>>>(out);
}

// round 14
// speedup vs baseline: 2.2217x; 1.0403x over previous
#include <cuda_runtime.h>
#include <cstdint>

// ---------------------------------------------------------------------------
// DynamicConvBlock: fused 65-tap combined depthwise conv + ReLU + 1x1 conv.
//   x:(8,192,96,96) f32 -> out:(8,64,96,96) f32
// Stage 0: prep_w_frag: W -> fp16 A-fragments (m16n8k16 lane order).
// Stage 1: conv kernel (frozen, ~31us) -> g_mid.
// Stage 2: pointwise_tc2: mma.sync.m16n8k16 f16, 2-pass split:
//          D = Wh*Bh + Wh*Bl  (W at fp16 precision, B at ~22 bits).
//          Warp = all 64 oc x 32 px (no B replication); block = 128 px.
// ---------------------------------------------------------------------------

#define NB   8
#define NC   192
#define NCP  96
#define NH   96
#define NW   96
#define HW   (NH*NW)     // 9216
#define NOC  64
#define TAPS 65
#define PROW 16
#define KS16 12          // 192 / 16

// scratch
__device__ float g_mid[(size_t)NB * NC * HW];      // 56.6 MB
__device__ uint4 g_wah[4 * KS16 * 32];             // A-fragments f16 (24 KB)

// ---- tap tables ------------------------------------------------------------
__device__ constexpr int SEC_DX[11]   = {-7,-5,-3,-2,-1, 0, 1, 2, 3, 5, 7};
__device__ constexpr int SEC_BASE[11] = {-7,-5,-3,-3,-3,-7,-3,-3,-3,-5,-7};
__device__ constexpr int SEC_W[11]    = {30,26,22,22,22,30,22,22,22,26,30};
__device__ constexpr int SEC_N[11]    = { 3, 3, 7, 7, 7,11, 7, 7, 7, 3, 3};
__device__ constexpr int SEC_OFF[11]  = { 0, 3, 6,13,20,27,38,45,52,59,62};

__device__ constexpr int DY_FLAT[TAPS] = {
    -7,0,7, -5,0,5,
    -3,-2,-1,0,1,2,3, -3,-2,-1,0,1,2,3, -3,-2,-1,0,1,2,3,
    -7,-5,-3,-2,-1,0,1,2,3,5,7,
    -3,-2,-1,0,1,2,3, -3,-2,-1,0,1,2,3, -3,-2,-1,0,1,2,3,
    -5,0,5, -7,0,7
};
__device__ constexpr int DX_FLAT[TAPS] = {
    -7,-7,-7, -5,-5,-5,
    -3,-3,-3,-3,-3,-3,-3, -2,-2,-2,-2,-2,-2,-2, -1,-1,-1,-1,-1,-1,-1,
     0,0,0,0,0,0,0,0,0,0,0,
     1,1,1,1,1,1,1, 2,2,2,2,2,2,2, 3,3,3,3,3,3,3,
     5,5,5, 7,7,7
};

// ---- helpers ---------------------------------------------------------------
__device__ __forceinline__ unsigned long long fma2_(unsigned long long a,
                                                    unsigned long long b,
                                                    unsigned long long c) {
    unsigned long long d;
    asm("fma.rn.f32x2 %0, %1, %2, %3;" : "=l"(d) : "l"(a), "l"(b), "l"(c));
    return d;
}
__device__ __forceinline__ float2 unpk2_(unsigned long long v) {
    float2 f;
    asm("mov.b64 {%0, %1}, %2;" : "=f"(f.x), "=f"(f.y) : "l"(v));
    return f;
}
// pack two f32 -> f16x2 (first arg -> low half)
__device__ __forceinline__ uint32_t packh(float lo, float hi) {
    uint32_t r;
    asm("cvt.rn.f16x2.f32 %0, %1, %2;" : "=r"(r) : "f"(hi), "f"(lo));
    return r;
}
// unpack f16x2 -> two f32
__device__ __forceinline__ float2 h2f2(uint32_t h) {
    float2 f;
    asm("{ .reg .b16 lo, hi; mov.b32 {lo, hi}, %2;"
        "  cvt.f32.f16 %0, lo; cvt.f32.f16 %1, hi; }"
        : "=f"(f.x), "=f"(f.y) : "r"(h));
    return f;
}
__device__ __forceinline__ void mma_f16(float* d, uint4 a,
                                        uint32_t b0, uint32_t b1) {
    asm("mma.sync.aligned.m16n8k16.row.col.f32.f16.f16.f32 "
        "{%0,%1,%2,%3}, {%4,%5,%6,%7}, {%8,%9}, {%0,%1,%2,%3};"
        : "+f"(d[0]), "+f"(d[1]), "+f"(d[2]), "+f"(d[3])
        : "r"(a.x), "r"(a.y), "r"(a.z), "r"(a.w), "r"(b0), "r"(b1));
}

// ---- fold the 7 weight tensors + a[] into one 65-tap weight ----------------
__device__ __forceinline__ float fold_weight(int c, int t,
                                             const float* __restrict__ a,
                                             const float* __restrict__ k1,
                                             const float* __restrict__ k3,
                                             const float* __restrict__ k5,
                                             const float* __restrict__ k7,
                                             const float* __restrict__ k3d5,
                                             const float* __restrict__ k3d7) {
    int dy = DY_FLAT[t], dx = DX_FLAT[t];
    float w = 0.0f;
    if (abs(dy) <= 3 && abs(dx) <= 3) w += a[4] * k7[c * 49 + (dy + 3) * 7 + (dx + 3)];
    if (abs(dy) <= 2 && abs(dx) <= 2) w += a[3] * k5[c * 25 + (dy + 2) * 5 + (dx + 2)];
    if (abs(dy) <= 1 && abs(dx) <= 1) w += (a[2] + a[5]) * k3[c * 9 + (dy + 1) * 3 + (dx + 1)];
    if (dy == 0 && dx == 0)           w += a[0] + a[1] * k1[c];
    if ((dy == -5 || dy == 0 || dy == 5) && (dx == -5 || dx == 0 || dx == 5))
        w += a[6] * k3d5[c * 9 + (dy / 5 + 1) * 3 + (dx / 5 + 1)];
    if ((dy == -7 || dy == 0 || dy == 7) && (dx == -7 || dx == 0 || dx == 7))
        w += a[7] * k3d7[c * 9 + (dy / 7 + 1) * 3 + (dx / 7 + 1)];
    return w;
}

// ---------------------------------------------------------------------------
// Stage 0: fp16 A-fragments for mma.m16n8k16.row (A = W[64,192]).
// Fragment f = mt*12+ks, lane l (r = 16mt + l/4, c = 16ks + 2*(l%4)):
//   a0 = {W[r][c],     W[r][c+1]}     a1 = {W[r+8][c],   W[r+8][c+1]}
//   a2 = {W[r][c+8],   W[r][c+9]}     a3 = {W[r+8][c+8], W[r+8][c+9]}
// ---------------------------------------------------------------------------
__global__ void prep_w_frag(const float* __restrict__ wp) {
    int i = blockIdx.x * 256 + threadIdx.x;
    if (i >= 4 * KS16 * 32) return;
    int lane = i & 31;
    int f    = i >> 5;
    int mt   = f / KS16;
    int ks   = f - mt * KS16;
    int r = mt * 16 + (lane >> 2);
    int c = ks * 16 + (lane & 3) * 2;

    g_wah[i] = make_uint4(
        packh(wp[r * NC + c],           wp[r * NC + c + 1]),
        packh(wp[(r + 8) * NC + c],     wp[(r + 8) * NC + c + 1]),
        packh(wp[r * NC + c + 8],       wp[r * NC + c + 9]),
        packh(wp[(r + 8) * NC + c + 8], wp[(r + 8) * NC + c + 9]));
}

// ---------------------------------------------------------------------------
// Stage 1: depthwise conv + ReLU (frozen, ~31us).
// ---------------------------------------------------------------------------
#define SM_ROWS 30
#define SM_PITCH 112

__global__ void __launch_bounds__(96)
conv_kernel(const float* __restrict__ x,
            const float* __restrict__ a,
            const float* __restrict__ k1,
            const float* __restrict__ k3,
            const float* __restrict__ k5,
            const float* __restrict__ k7,
            const float* __restrict__ k3d5,
            const float* __restrict__ k3d7) {
    __shared__ float2 sm[SM_ROWS][SM_PITCH];
    __shared__ float2 sw[TAPS];

    const int tid = threadIdx.x;
    const int bc  = blockIdx.y;
    const int b   = bc / NCP;
    const int cp  = bc - b * NCP;
    const int c0  = cp * 2;
    const int h0  = blockIdx.x * PROW;

    {
        float4* smf = reinterpret_cast<float4*>(&sm[0][0]);
        for (int i = tid; i < SM_ROWS * SM_PITCH / 2; i += 96)
            smf[i] = make_float4(0.f, 0.f, 0.f, 0.f);
    }

    for (int i = tid; i < 2 * TAPS; i += 96) {
        int t = i >> 1, half = i & 1;
        float w = fold_weight(c0 + half, t, a, k1, k3, k5, k7, k3d5, k3d7);
        reinterpret_cast<float*>(&sw[t])[half] = w;
    }
    __syncthreads();

    const size_t xbase = ((size_t)b * NC + c0) * HW;
    {
        const int r0 = (h0 >= 7)       ? 0  : 7 - h0;
        const int r1 = (h0 <= NH - 23) ? 30 : (NH + 7 - h0);
        const float* px0 = x + xbase + (size_t)(h0 - 7) * NW + tid;
        for (int r = r0; r < r1; r++) {
            float2 v;
            v.x = px0[(size_t)r * NW];
            v.y = px0[(size_t)r * NW + HW];
            sm[r][tid + 7] = v;
        }
    }
    __syncthreads();

    const int col = tid + 7;
    const unsigned long long* swq = reinterpret_cast<const unsigned long long*>(sw);

    unsigned long long acc[PROW];
#pragma unroll
    for (int p = 0; p < PROW; p++) acc[p] = 0ull;

#pragma unroll
    for (int s = 0; s < 11; s++) {
        const int bse = SEC_BASE[s];
        const int wl  = SEC_W[s];
        const int nd  = SEC_N[s];
        const int off = SEC_OFF[s];
        const int cx  = col + SEC_DX[s];

        unsigned long long wv[11];
#pragma unroll
        for (int j = 0; j < nd; j++) wv[j] = swq[off + j];

#pragma unroll
        for (int i = 0; i < wl; i++) {
            unsigned long long v =
                *reinterpret_cast<const unsigned long long*>(&sm[bse + 7 + i][cx]);
#pragma unroll
            for (int j = 0; j < nd; j++) {
                const int p = i - (DY_FLAT[off + j] - bse);
                if (p >= 0 && p < PROW)
                    acc[p] = fma2_(v, wv[j], acc[p]);
            }
        }
    }

    float* m0 = g_mid + xbase + (size_t)h0 * NW + tid;
#pragma unroll
    for (int p = 0; p < PROW; p++) {
        float2 v = unpk2_(acc[p]);
        v.x = fmaxf(v.x, 0.0f);
        v.y = fmaxf(v.y, 0.0f);
        m0[(size_t)p * NW]      = v.x;
        m0[(size_t)p * NW + HW] = v.y;
    }
}

// ---------------------------------------------------------------------------
// Stage 2: pointwise 1x1 conv 192->64, mma.sync.m16n8k16 f16, 2-pass:
//   D = Wh*Bh + Wh*Bl   (W at fp16; B split hi/lo ~22 bits)
// Block = 128 thr (4 warps), block tile = 64 oc x 128 px.
// Warp = ALL 4 m-slabs x 4 n8-subtiles (32 px) -> no B replication.
// B-fragment (row.col): n = n0 + l/4; b0 = {M[k0][n],M[k0+1][n]},
//   b1 = {M[k0+8][n],M[k0+9][n]}, k0 = 16ks + 2*(l%4).
// C-fragment: c0,c1 = row l/4, cols 2*(l%4)+{0,1}; c2,c3 = row+8.
// ---------------------------------------------------------------------------
__global__ void __launch_bounds__(128)
pointwise_tc2(float* __restrict__ out) {
    const int tid  = threadIdx.x;
    const int lane = tid & 31;
    const int wt   = tid >> 5;                      // warp's px quarter

    const int pixglob = blockIdx.x * 128 + wt * 32; // 128 | 9216
    const int b   = pixglob / HW;
    const int pix = pixglob - b * HW;

    const int kr2 = (lane & 3) * 2;                 // k pair base
    const int np  = lane >> 2;                      // px within subtile

    const float* midb = g_mid + (size_t)b * NC * HW + pix + np;
    const uint4* wah = g_wah + lane;

    float acc[4][4][4];                             // [mt][subtile][4]
#pragma unroll
    for (int m = 0; m < 4; m++)
#pragma unroll
        for (int s = 0; s < 4; s++)
#pragma unroll
            for (int q = 0; q < 4; q++) acc[m][s][q] = 0.0f;

#pragma unroll 1
    for (int ks = 0; ks < KS16; ks++) {
        // A fragments: 4 m-slabs (L1-hot table)
        uint4 Ah[4];
#pragma unroll
        for (int m = 0; m < 4; m++)
            Ah[m] = wah[(m * KS16 + ks) * 32];

        // B values: 4 subtiles x 4 k-rows, all loads issued first (MLP=16)
        const float* mk = midb + (size_t)(ks * 16 + kr2) * HW;
        float v[4][4];
#pragma unroll
        for (int s = 0; s < 4; s++) {
            v[s][0] = mk[s * 8];
            v[s][1] = mk[(size_t)1 * HW + s * 8];
            v[s][2] = mk[(size_t)8 * HW + s * 8];
            v[s][3] = mk[(size_t)9 * HW + s * 8];
        }

#pragma unroll
        for (int s = 0; s < 4; s++) {
            uint32_t bh0 = packh(v[s][0], v[s][1]);
            uint32_t bh1 = packh(v[s][2], v[s][3]);
            float2 r0 = h2f2(bh0), r1 = h2f2(bh1);
            uint32_t bl0 = packh(v[s][0] - r0.x, v[s][1] - r0.y);
            uint32_t bl1 = packh(v[s][2] - r1.x, v[s][3] - r1.y);
#pragma unroll
            for (int m = 0; m < 4; m++) {
                mma_f16(acc[m][s], Ah[m], bh0, bh1);
                mma_f16(acc[m][s], Ah[m], bl0, bl1);
            }
        }
    }

    // epilogue
    const int g  = lane >> 2;
    const int t4 = lane & 3;
#pragma unroll
    for (int m = 0; m < 4; m++) {
        float* o0 = out + ((size_t)(b * NOC + m * 16 + g)) * HW + pix + 2 * t4;
        float* o1 = o0 + (size_t)8 * HW;
#pragma unroll
        for (int s = 0; s < 4; s++) {
            *reinterpret_cast<float2*>(o0 + s * 8) =
                make_float2(acc[m][s][0], acc[m][s][1]);
            *reinterpret_cast<float2*>(o1 + s * 8) =
                make_float2(acc[m][s][2], acc[m][s][3]);
        }
    }
}

// ---------------------------------------------------------------------------
extern "C" void kernel_launch(void* const* d_in, const int* in_sizes, int n_in,
                              void* d_out, int out_size) {
    const float* x    = (const float*)d_in[0];
    const float* a    = (const float*)d_in[1];
    const float* k1   = (const float*)d_in[2];
    const float* k3   = (const float*)d_in[3];
    const float* k5   = (const float*)d_in[4];
    const float* k7   = (const float*)d_in[5];
    const float* k3d5 = (const float*)d_in[6];
    const float* k3d7 = (const float*)d_in[7];
    const float* wp   = (const float*)d_in[8];
    float* out = (float*)d_out;

    prep_w_frag<<<(4 * KS16 * 32 + 255) / 256, 256>>>(wp);
    conv_kernel<<<dim3(NH / PROW, NB * NCP), 96>>>(x, a, k1, k3, k5, k7, k3d5, k3d7);
    pointwise_tc2<<<NB * HW / 128, 128>>>(out);
}

// round 15
// speedup vs baseline: 2.3530x; 1.0591x over previous
#include <cuda_runtime.h>
#include <cstdint>

// ---------------------------------------------------------------------------
// DynamicConvBlock: fused 65-tap combined depthwise conv + ReLU + 1x1 conv.
//   x:(8,192,96,96) f32 -> out:(8,64,96,96) f32
// Stage 0: prep_w_frag: W -> fp16 A-fragments (m16n8k16 lane order).
// Stage 1: conv kernel -> g_midh: fp16x2 CHANNEL-PAIR packed mid
//          ([b][cp][px], 28.3 MB) = ready-made mma B-fragment registers.
// Stage 2: pointwise_tc2: mma.sync.m16n8k16 f16 single pass; B regs loaded
//          directly (1 LDG.32 each, zero conversions).
// ---------------------------------------------------------------------------

#define NB   8
#define NC   192
#define NCP  96
#define NH   96
#define NW   96
#define HW   (NH*NW)     // 9216
#define NOC  64
#define TAPS 65
#define PROW 16
#define KS16 12          // 192 / 16

// scratch
__device__ uint32_t g_midh[(size_t)NB * NCP * HW]; // 28.3 MB fp16x2 (ch pair)
__device__ uint4 g_wah[4 * KS16 * 32];             // A-fragments f16 (24 KB)

// ---- tap tables ------------------------------------------------------------
__device__ constexpr int SEC_DX[11]   = {-7,-5,-3,-2,-1, 0, 1, 2, 3, 5, 7};
__device__ constexpr int SEC_BASE[11] = {-7,-5,-3,-3,-3,-7,-3,-3,-3,-5,-7};
__device__ constexpr int SEC_W[11]    = {30,26,22,22,22,30,22,22,22,26,30};
__device__ constexpr int SEC_N[11]    = { 3, 3, 7, 7, 7,11, 7, 7, 7, 3, 3};
__device__ constexpr int SEC_OFF[11]  = { 0, 3, 6,13,20,27,38,45,52,59,62};

__device__ constexpr int DY_FLAT[TAPS] = {
    -7,0,7, -5,0,5,
    -3,-2,-1,0,1,2,3, -3,-2,-1,0,1,2,3, -3,-2,-1,0,1,2,3,
    -7,-5,-3,-2,-1,0,1,2,3,5,7,
    -3,-2,-1,0,1,2,3, -3,-2,-1,0,1,2,3, -3,-2,-1,0,1,2,3,
    -5,0,5, -7,0,7
};
__device__ constexpr int DX_FLAT[TAPS] = {
    -7,-7,-7, -5,-5,-5,
    -3,-3,-3,-3,-3,-3,-3, -2,-2,-2,-2,-2,-2,-2, -1,-1,-1,-1,-1,-1,-1,
     0,0,0,0,0,0,0,0,0,0,0,
     1,1,1,1,1,1,1, 2,2,2,2,2,2,2, 3,3,3,3,3,3,3,
     5,5,5, 7,7,7
};

// ---- helpers ---------------------------------------------------------------
__device__ __forceinline__ unsigned long long fma2_(unsigned long long a,
                                                    unsigned long long b,
                                                    unsigned long long c) {
    unsigned long long d;
    asm("fma.rn.f32x2 %0, %1, %2, %3;" : "=l"(d) : "l"(a), "l"(b), "l"(c));
    return d;
}
__device__ __forceinline__ float2 unpk2_(unsigned long long v) {
    float2 f;
    asm("mov.b64 {%0, %1}, %2;" : "=f"(f.x), "=f"(f.y) : "l"(v));
    return f;
}
// pack two f32 -> f16x2 (first arg -> low half)
__device__ __forceinline__ uint32_t packh(float lo, float hi) {
    uint32_t r;
    asm("cvt.rn.f16x2.f32 %0, %1, %2;" : "=r"(r) : "f"(hi), "f"(lo));
    return r;
}
__device__ __forceinline__ void mma_f16(float* d, uint4 a,
                                        uint32_t b0, uint32_t b1) {
    asm("mma.sync.aligned.m16n8k16.row.col.f32.f16.f16.f32 "
        "{%0,%1,%2,%3}, {%4,%5,%6,%7}, {%8,%9}, {%0,%1,%2,%3};"
        : "+f"(d[0]), "+f"(d[1]), "+f"(d[2]), "+f"(d[3])
        : "r"(a.x), "r"(a.y), "r"(a.z), "r"(a.w), "r"(b0), "r"(b1));
}

// ---- fold the 7 weight tensors + a[] into one 65-tap weight ----------------
__device__ __forceinline__ float fold_weight(int c, int t,
                                             const float* __restrict__ a,
                                             const float* __restrict__ k1,
                                             const float* __restrict__ k3,
                                             const float* __restrict__ k5,
                                             const float* __restrict__ k7,
                                             const float* __restrict__ k3d5,
                                             const float* __restrict__ k3d7) {
    int dy = DY_FLAT[t], dx = DX_FLAT[t];
    float w = 0.0f;
    if (abs(dy) <= 3 && abs(dx) <= 3) w += a[4] * k7[c * 49 + (dy + 3) * 7 + (dx + 3)];
    if (abs(dy) <= 2 && abs(dx) <= 2) w += a[3] * k5[c * 25 + (dy + 2) * 5 + (dx + 2)];
    if (abs(dy) <= 1 && abs(dx) <= 1) w += (a[2] + a[5]) * k3[c * 9 + (dy + 1) * 3 + (dx + 1)];
    if (dy == 0 && dx == 0)           w += a[0] + a[1] * k1[c];
    if ((dy == -5 || dy == 0 || dy == 5) && (dx == -5 || dx == 0 || dx == 5))
        w += a[6] * k3d5[c * 9 + (dy / 5 + 1) * 3 + (dx / 5 + 1)];
    if ((dy == -7 || dy == 0 || dy == 7) && (dx == -7 || dx == 0 || dx == 7))
        w += a[7] * k3d7[c * 9 + (dy / 7 + 1) * 3 + (dx / 7 + 1)];
    return w;
}

// ---------------------------------------------------------------------------
// Stage 0: fp16 A-fragments for mma.m16n8k16.row (A = W[64,192]).
// Fragment f = mt*12+ks, lane l (r = 16mt + l/4, c = 16ks + 2*(l%4)):
//   a0 = {W[r][c],     W[r][c+1]}     a1 = {W[r+8][c],   W[r+8][c+1]}
//   a2 = {W[r][c+8],   W[r][c+9]}     a3 = {W[r+8][c+8], W[r+8][c+9]}
// ---------------------------------------------------------------------------
__global__ void prep_w_frag(const float* __restrict__ wp) {
    int i = blockIdx.x * 256 + threadIdx.x;
    if (i >= 4 * KS16 * 32) return;
    int lane = i & 31;
    int f    = i >> 5;
    int mt   = f / KS16;
    int ks   = f - mt * KS16;
    int r = mt * 16 + (lane >> 2);
    int c = ks * 16 + (lane & 3) * 2;

    g_wah[i] = make_uint4(
        packh(wp[r * NC + c],           wp[r * NC + c + 1]),
        packh(wp[(r + 8) * NC + c],     wp[(r + 8) * NC + c + 1]),
        packh(wp[r * NC + c + 8],       wp[r * NC + c + 9]),
        packh(wp[(r + 8) * NC + c + 8], wp[(r + 8) * NC + c + 9]));
}

// ---------------------------------------------------------------------------
// Stage 1: depthwise conv + ReLU -> fp16x2 channel-pair mid.
// ---------------------------------------------------------------------------
#define SM_ROWS 30
#define SM_PITCH 112

__global__ void __launch_bounds__(96)
conv_kernel(const float* __restrict__ x,
            const float* __restrict__ a,
            const float* __restrict__ k1,
            const float* __restrict__ k3,
            const float* __restrict__ k5,
            const float* __restrict__ k7,
            const float* __restrict__ k3d5,
            const float* __restrict__ k3d7) {
    __shared__ float2 sm[SM_ROWS][SM_PITCH];
    __shared__ float2 sw[TAPS];

    const int tid = threadIdx.x;
    const int bc  = blockIdx.y;                     // b*96 + cp
    const int b   = bc / NCP;
    const int cp  = bc - b * NCP;
    const int c0  = cp * 2;
    const int h0  = blockIdx.x * PROW;

    {
        float4* smf = reinterpret_cast<float4*>(&sm[0][0]);
        for (int i = tid; i < SM_ROWS * SM_PITCH / 2; i += 96)
            smf[i] = make_float4(0.f, 0.f, 0.f, 0.f);
    }

    for (int i = tid; i < 2 * TAPS; i += 96) {
        int t = i >> 1, half = i & 1;
        float w = fold_weight(c0 + half, t, a, k1, k3, k5, k7, k3d5, k3d7);
        reinterpret_cast<float*>(&sw[t])[half] = w;
    }
    __syncthreads();

    const size_t xbase = ((size_t)b * NC + c0) * HW;
    {
        const int r0 = (h0 >= 7)       ? 0  : 7 - h0;
        const int r1 = (h0 <= NH - 23) ? 30 : (NH + 7 - h0);
        const float* px0 = x + xbase + (size_t)(h0 - 7) * NW + tid;
        for (int r = r0; r < r1; r++) {
            float2 v;
            v.x = px0[(size_t)r * NW];
            v.y = px0[(size_t)r * NW + HW];
            sm[r][tid + 7] = v;
        }
    }
    __syncthreads();

    const int col = tid + 7;
    const unsigned long long* swq = reinterpret_cast<const unsigned long long*>(sw);

    unsigned long long acc[PROW];
#pragma unroll
    for (int p = 0; p < PROW; p++) acc[p] = 0ull;

#pragma unroll
    for (int s = 0; s < 11; s++) {
        const int bse = SEC_BASE[s];
        const int wl  = SEC_W[s];
        const int nd  = SEC_N[s];
        const int off = SEC_OFF[s];
        const int cx  = col + SEC_DX[s];

        unsigned long long wv[11];
#pragma unroll
        for (int j = 0; j < nd; j++) wv[j] = swq[off + j];

#pragma unroll
        for (int i = 0; i < wl; i++) {
            unsigned long long v =
                *reinterpret_cast<const unsigned long long*>(&sm[bse + 7 + i][cx]);
#pragma unroll
            for (int j = 0; j < nd; j++) {
                const int p = i - (DY_FLAT[off + j] - bse);
                if (p >= 0 && p < PROW)
                    acc[p] = fma2_(v, wv[j], acc[p]);
            }
        }
    }

    // ---- ReLU + pack channel pair to fp16x2, single coalesced store ----
    uint32_t* m0 = g_midh + (size_t)bc * HW + (size_t)h0 * NW + tid;
#pragma unroll
    for (int p = 0; p < PROW; p++) {
        float2 v = unpk2_(acc[p]);
        v.x = fmaxf(v.x, 0.0f);
        v.y = fmaxf(v.y, 0.0f);
        m0[(size_t)p * NW] = packh(v.x, v.y);       // low = even ch, high = odd
    }
}

// ---------------------------------------------------------------------------
// Stage 2: pointwise 1x1 conv 192->64, mma.sync.m16n8k16 f16, SINGLE pass.
// Block = 128 thr (4 warps), block tile = 64 oc x 128 px; warp = 64 oc x 32 px
// (no B replication). B regs loaded directly from g_midh:
//   b0 = g_midh[b][8ks + l%4    ][pix + l/4 + 8s]   ({M[k0],M[k0+1]})
//   b1 = g_midh[b][8ks + l%4 + 4][ same px ]        ({M[k0+8],M[k0+9]})
// C-fragment: c0,c1 = row l/4, cols 2*(l%4)+{0,1}; c2,c3 = row+8.
// ---------------------------------------------------------------------------
__global__ void __launch_bounds__(128)
pointwise_tc2(float* __restrict__ out) {
    const int tid  = threadIdx.x;
    const int lane = tid & 31;
    const int wt   = tid >> 5;                      // warp's px quarter

    const int pixglob = blockIdx.x * 128 + wt * 32; // 128 | 9216
    const int b   = pixglob / HW;
    const int pix = pixglob - b * HW;

    const int kr = lane & 3;                        // k-pair row
    const int np = lane >> 2;                       // px within subtile

    const uint32_t* midb = g_midh + (size_t)b * NCP * HW + pix + np;
    const uint4* wah = g_wah + lane;

    float acc[4][4][4];                             // [mt][subtile][4]
#pragma unroll
    for (int m = 0; m < 4; m++)
#pragma unroll
        for (int s = 0; s < 4; s++)
#pragma unroll
            for (int q = 0; q < 4; q++) acc[m][s][q] = 0.0f;

#pragma unroll 1
    for (int ks = 0; ks < KS16; ks++) {
        // A fragments: 4 m-slabs (L1-hot table)
        uint4 Ah[4];
#pragma unroll
        for (int m = 0; m < 4; m++)
            Ah[m] = wah[(m * KS16 + ks) * 32];

        // B fragments: direct fp16x2 loads, all issued first (MLP=8)
        const uint32_t* mk = midb + (size_t)(ks * 8 + kr) * HW;
        uint32_t b0[4], b1[4];
#pragma unroll
        for (int s = 0; s < 4; s++) {
            b0[s] = mk[s * 8];
            b1[s] = mk[(size_t)4 * HW + s * 8];
        }

#pragma unroll
        for (int s = 0; s < 4; s++) {
#pragma unroll
            for (int m = 0; m < 4; m++)
                mma_f16(acc[m][s], Ah[m], b0[s], b1[s]);
        }
    }

    // epilogue
    const int g  = lane >> 2;
    const int t4 = lane & 3;
#pragma unroll
    for (int m = 0; m < 4; m++) {
        float* o0 = out + ((size_t)(b * NOC + m * 16 + g)) * HW + pix + 2 * t4;
        float* o1 = o0 + (size_t)8 * HW;
#pragma unroll
        for (int s = 0; s < 4; s++) {
            *reinterpret_cast<float2*>(o0 + s * 8) =
                make_float2(acc[m][s][0], acc[m][s][1]);
            *reinterpret_cast<float2*>(o1 + s * 8) =
                make_float2(acc[m][s][2], acc[m][s][3]);
        }
    }
}

// ---------------------------------------------------------------------------
extern "C" void kernel_launch(void* const* d_in, const int* in_sizes, int n_in,
                              void* d_out, int out_size) {
    const float* x    = (const float*)d_in[0];
    const float* a    = (const float*)d_in[1];
    const float* k1   = (const float*)d_in[2];
    const float* k3   = (const float*)d_in[3];
    const float* k5   = (const float*)d_in[4];
    const float* k7   = (const float*)d_in[5];
    const float* k3d5 = (const float*)d_in[6];
    const float* k3d7 = (const float*)d_in[7];
    const float* wp   = (const float*)d_in[8];
    float* out = (float*)d_out;

    prep_w_frag<<<(4 * KS16 * 32 + 255) / 256, 256>>>(wp);
    conv_kernel<<<dim3(NH / PROW, NB * NCP), 96>>>(x, a, k1, k3, k5, k7, k3d5, k3d7);
    pointwise_tc2<<<NB * HW / 128, 128>>>(out);
}